// round 5
// baseline (speedup 1.0000x reference)
#include <cuda_runtime.h>
#include <cstdint>

// ============================================================================
// FlattenedObsEncoder: out[16384,1024] = (gather(W_embed,x)+b_embed) @ W_dense + b_dense
// tf32 mma.sync GEMM (base sm_103 ptxas target -> HMMA path).
// CTA tile 128(M) x 256(N), 256 threads (8 warps, warp tile 32x128),
// 3-stage cp.async pipeline for B, in-loop A gather.
// ============================================================================

#define B_SZ   16384
#define P_SZ   256
#define K_SZ   1024
#define N_SZ   1024
#define MT     128            // M rows per CTA
#define NT     256            // N cols per CTA
#define KC     32             // K per chunk
#define NCHUNK (K_SZ / KC)    // 32
#define THREADS 256
#define SA     36             // A smem row stride (floats)
#define SB     36             // B smem row stride (floats)
#define A_ST   (MT * SA)      // 4608 floats
#define B_ST   (NT * SB)      // 9216 floats
#define STAGE_F (A_ST + B_ST) // 13824 floats per stage
#define NSTAGE 3
#define SMEM_BYTES (STAGE_F * NSTAGE * 4)   // 165,888 B

// W_dense transposed to [N][K], tf32-rounded (static device global).
__device__ float g_WdT[(size_t)N_SZ * K_SZ];

// ---------------------------------------------------------------------------
__device__ __forceinline__ uint32_t smem_u32(const void* p) {
    uint32_t a;
    asm("{ .reg .u64 t; cvta.to.shared.u64 t, %1; cvt.u32.u64 %0, t; }" : "=r"(a) : "l"(p));
    return a;
}
__device__ __forceinline__ float tf32_rn(float v) {
    float r;
    asm("cvt.rna.tf32.f32 %0, %1;" : "=f"(r) : "f"(v));
    return r;
}
__device__ __forceinline__ void cp16(uint32_t s, const void* g) {
    asm volatile("cp.async.cg.shared.global [%0], [%1], 16;" :: "r"(s), "l"(g));
}
#define CP_COMMIT() asm volatile("cp.async.commit_group;" ::: "memory")
#define CP_WAIT1()  asm volatile("cp.async.wait_group 1;" ::: "memory")

// ---------------------------------------------------------------------------
// Prepass: transpose W_dense [K,N] -> g_WdT [N,K], tf32 rounding.
// ---------------------------------------------------------------------------
__global__ void transpose_wd_kernel(const float* __restrict__ Wd) {
    __shared__ float t[32][33];
    const int tx = threadIdx.x, ty = threadIdx.y;
    const int n = blockIdx.x * 32 + tx;
    const int k = blockIdx.y * 32 + ty;
#pragma unroll
    for (int j = 0; j < 32; j += 8)
        t[ty + j][tx] = Wd[(size_t)(k + j) * N_SZ + n];
    __syncthreads();
    const int ko = blockIdx.y * 32 + tx;
    const int no = blockIdx.x * 32 + ty;
#pragma unroll
    for (int j = 0; j < 32; j += 8)
        g_WdT[(size_t)(no + j) * K_SZ + ko] = tf32_rn(t[tx][ty + j]);
}

// ---------------------------------------------------------------------------
// One k-step: warp tile 32(M) x 128(N) = 2 m-tiles x 16 n-tiles.
// ---------------------------------------------------------------------------
__device__ __forceinline__ void compute_kstep(
    const float* __restrict__ As_, const float* __restrict__ Bs_,
    int warp_m, int warp_n, int g, int t4, int k0, float c[2][16][4]) {
    uint32_t a[2][4];
#pragma unroll
    for (int i = 0; i < 2; ++i) {
        const int r = warp_m * 32 + i * 16 + g;
        a[i][0] = __float_as_uint(As_[r * SA + k0 + t4]);
        a[i][1] = __float_as_uint(As_[(r + 8) * SA + k0 + t4]);
        a[i][2] = __float_as_uint(As_[r * SA + k0 + t4 + 4]);
        a[i][3] = __float_as_uint(As_[(r + 8) * SA + k0 + t4 + 4]);
    }
    uint32_t b[16][2];
#pragma unroll
    for (int j = 0; j < 16; ++j) {
        const int nn = warp_n * 128 + j * 8 + g;
        b[j][0] = __float_as_uint(Bs_[nn * SB + k0 + t4]);
        b[j][1] = __float_as_uint(Bs_[nn * SB + k0 + t4 + 4]);
    }
#pragma unroll
    for (int j = 0; j < 16; ++j)
#pragma unroll
        for (int i = 0; i < 2; ++i) {
            asm volatile(
                "mma.sync.aligned.m16n8k8.row.col.f32.tf32.tf32.f32 "
                "{%0,%1,%2,%3}, {%4,%5,%6,%7}, {%8,%9}, {%0,%1,%2,%3};"
                : "+f"(c[i][j][0]), "+f"(c[i][j][1]),
                  "+f"(c[i][j][2]), "+f"(c[i][j][3])
                : "r"(a[i][0]), "r"(a[i][1]), "r"(a[i][2]), "r"(a[i][3]),
                  "r"(b[j][0]), "r"(b[j][1]));
        }
}

// ---------------------------------------------------------------------------
// Main GEMM kernel.  SMEM: 3 stages of [A: MT x SA | B: NT x SB].
// ---------------------------------------------------------------------------
__global__ void __launch_bounds__(THREADS, 1)
enc_gemm_kernel(const int* __restrict__ x, const float* __restrict__ We,
                const float* __restrict__ be, const float* __restrict__ bd,
                float* __restrict__ out) {
    extern __shared__ float smem[];
    const uint32_t sbase = smem_u32(smem);

    const int tid = threadIdx.x;
    const int wid = tid >> 5, lane = tid & 31;
    const int g = lane >> 2, t4 = lane & 3;
    const int warp_m = wid & 3;      // 4 x 32 = 128 M
    const int warp_n = wid >> 2;     // 2 x 128 = 256 N
    const int n0 = blockIdx.x * NT;
    const int m0 = blockIdx.y * MT;

    // A-gather mapping: 2 threads per M row, 4 positions (16 floats) each.
    const int arow = tid >> 1, ahalf = tid & 1;
    const int* xptr = x + (size_t)(m0 + arow) * P_SZ + ahalf * 4;
    const float4* We4 = (const float4*)We;
    const float be0 = be[0], be1 = be[1], be2 = be[2], be3 = be[3];
    const uint32_t aDstOff = (uint32_t)arow * (SA * 4u) + (uint32_t)ahalf * 64u;

    // B-copy mapping: NT*KC/4 = 2048 16B chunks / 256 threads = 8 each.
    const float* bsrc = g_WdT + (size_t)n0 * K_SZ;
    const int brow = tid >> 3, bseg = tid & 7;   // +32 rows per step

    float c[2][16][4];
#pragma unroll
    for (int i = 0; i < 2; ++i)
#pragma unroll
        for (int j = 0; j < 16; ++j)
#pragma unroll
            for (int q = 0; q < 4; ++q) c[i][j][q] = 0.0f;

    auto stageA = [&](int s) -> float* { return smem + (size_t)s * STAGE_F; };
    auto stageB = [&](int s) -> float* { return smem + (size_t)s * STAGE_F + A_ST; };
    auto stageAaddr = [&](int s) -> uint32_t { return sbase + (uint32_t)s * (STAGE_F * 4u); };
    auto stageBaddr = [&](int s) -> uint32_t { return sbase + (uint32_t)s * (STAGE_F * 4u) + A_ST * 4u; };

    auto copyB = [&](int ch, int s) {
        const uint32_t bA = stageBaddr(s);
        const float* src = bsrc + (size_t)ch * KC;
#pragma unroll
        for (int i = 0; i < 8; ++i) {
            const int row = brow + i * 32;
            cp16(bA + (uint32_t)row * (SB * 4u) + (uint32_t)bseg * 16u,
                 src + (size_t)row * K_SZ + bseg * 4);
        }
    };
    auto stsA = [&](int s, int p, float4 e) {
        const uint32_t vx = __float_as_uint(tf32_rn(e.x + be0));
        const uint32_t vy = __float_as_uint(tf32_rn(e.y + be1));
        const uint32_t vz = __float_as_uint(tf32_rn(e.z + be2));
        const uint32_t vw = __float_as_uint(tf32_rn(e.w + be3));
        asm volatile("st.shared.v4.b32 [%0], {%1,%2,%3,%4};"
                     :: "r"(stageAaddr(s) + aDstOff + (uint32_t)p * 16u),
                        "r"(vx), "r"(vy), "r"(vz), "r"(vw) : "memory");
    };
    auto gatherA = [&](int ch, int s) {
        const int4 xi = *(const int4*)(xptr + ch * 8);
        stsA(s, 0, __ldg(We4 + xi.x));
        stsA(s, 1, __ldg(We4 + xi.y));
        stsA(s, 2, __ldg(We4 + xi.z));
        stsA(s, 3, __ldg(We4 + xi.w));
    };

    // ---- prologue: A(0)->s0; B(0)->s0; B(1)->s1 ----
    gatherA(0, 0);
    copyB(0, 0); CP_COMMIT();
    copyB(1, 1); CP_COMMIT();

    // ---- mainloop ----
    for (int ch = 0; ch < NCHUNK; ++ch) {
        const int st = ch % 3;
        const bool more = (ch + 1 < NCHUNK);

        CP_WAIT1();              // B(ch) landed (B(ch+1) may still be in flight)
        __syncthreads();         // A(ch) STS + B(ch) visible; stage (ch+2)%3 free

        if (ch + 2 < NCHUNK) copyB(ch + 2, (ch + 2) % 3);
        CP_COMMIT();             // keep one-group-per-iteration cadence

        // early: load next chunk's x indices (hide L2 latency under MMAs)
        int4 xi = {0, 0, 0, 0};
        if (more) xi = *(const int4*)(xptr + (ch + 1) * 8);

        const float* As_ = stageA(st);
        const float* Bs_ = stageB(st);

        compute_kstep(As_, Bs_, warp_m, warp_n, g, t4, 0,  c);
        compute_kstep(As_, Bs_, warp_m, warp_n, g, t4, 8,  c);

        float4 e0, e1, e2, e3;
        if (more) {
            e0 = __ldg(We4 + xi.x); e1 = __ldg(We4 + xi.y);
            e2 = __ldg(We4 + xi.z); e3 = __ldg(We4 + xi.w);
        }

        compute_kstep(As_, Bs_, warp_m, warp_n, g, t4, 16, c);
        compute_kstep(As_, Bs_, warp_m, warp_n, g, t4, 24, c);

        if (more) {
            const int ns = (ch + 1) % 3;
            stsA(ns, 0, e0); stsA(ns, 1, e1);
            stsA(ns, 2, e2); stsA(ns, 3, e3);
        }
    }

    // ---- epilogue: accum + b_dense -> out ----
#pragma unroll
    for (int i = 0; i < 2; ++i) {
        const size_t r0 = (size_t)(m0 + warp_m * 32 + i * 16 + g);
#pragma unroll
        for (int j = 0; j < 16; ++j) {
            const int col = n0 + warp_n * 128 + j * 8 + t4 * 2;
            const float2 bb = *(const float2*)(bd + col);
            float2 v0, v1;
            v0.x = c[i][j][0] + bb.x;  v0.y = c[i][j][1] + bb.y;
            v1.x = c[i][j][2] + bb.x;  v1.y = c[i][j][3] + bb.y;
            *(float2*)(out + r0 * N_SZ + col)       = v0;
            *(float2*)(out + (r0 + 8) * N_SZ + col) = v1;
        }
    }
}

// ---------------------------------------------------------------------------
// kernel_launch
// ---------------------------------------------------------------------------
extern "C" void kernel_launch(void* const* d_in, const int* in_sizes, int n_in,
                              void* d_out, int out_size) {
    const int*   x  = (const int*)d_in[0];
    const float* We = (const float*)d_in[1];
    const float* be = (const float*)d_in[2];
    const float* Wd = (const float*)d_in[3];
    const float* bd = (const float*)d_in[4];
    float* out = (float*)d_out;

    // Opt into >48KB dynamic smem (only when NOT capturing; the harness runs
    // one uncaptured correctness call first, so the attribute persists).
    cudaStreamCaptureStatus cs = cudaStreamCaptureStatusNone;
    cudaError_t qerr = cudaStreamIsCapturing((cudaStream_t)0, &cs);
    const bool capturing = (qerr != cudaSuccess) || (cs != cudaStreamCaptureStatusNone);
    if (!capturing) {
        cudaFuncSetAttribute(enc_gemm_kernel,
                             cudaFuncAttributeMaxDynamicSharedMemorySize, SMEM_BYTES);
    }
    (void)cudaGetLastError();

    transpose_wd_kernel<<<dim3(N_SZ / 32, K_SZ / 32), dim3(32, 8)>>>(Wd);
    enc_gemm_kernel<<<dim3(N_SZ / NT, B_SZ / MT), THREADS, SMEM_BYTES>>>(x, We, be, bd, out);
}

// round 6
// speedup vs baseline: 1.4097x; 1.4097x over previous
#include <cuda_runtime.h>
#include <cstdint>

// ============================================================================
// FlattenedObsEncoder: out[16384,1024] = (gather(W_embed,x)+b_embed) @ W_dense + b_dense
// tf32 mma.sync GEMM (base sm_103 ptxas target -> HMMA path).
// CTA tile 128(M) x 128(N), 256 threads (8 warps, warp tile 32x64), 2 CTAs/SM.
// B pre-permuted into HMMA fragment order by the prepass -> 4x LDS.128 per kstep.
// ============================================================================

#define B_SZ   16384
#define P_SZ   256
#define K_SZ   1024
#define N_SZ   1024
#define MT     128
#define NT     128
#define KC     32
#define NCHUNK (K_SZ / KC)    // 32
#define THREADS 256
#define SA     36                    // A smem row stride (floats): conflict-free
#define A_ST   (MT * SA)             // 4608 floats
#define B_ST   (NT * KC)             // 4096 floats (fragment-packed, no pad needed)
#define STAGE_F (A_ST + B_ST)        // 8704 floats
#define NSTAGE 3
#define SMEM_BYTES (STAGE_F * NSTAGE * 4)   // 104,448 B -> 2 CTAs/SM

// W_dense permuted into HMMA B-fragment order, tf32-rounded:
// float index = nb*16384 + ks*128 + (g*4+t4)*4 + jj*2 + h
//   where n = nb*16 + jj*8 + g,  k = ks*8 + t4 + 4*h
__device__ float g_WdT[(size_t)N_SZ * K_SZ];

// ---------------------------------------------------------------------------
__device__ __forceinline__ uint32_t smem_u32(const void* p) {
    uint32_t a;
    asm("{ .reg .u64 t; cvta.to.shared.u64 t, %1; cvt.u32.u64 %0, t; }" : "=r"(a) : "l"(p));
    return a;
}
__device__ __forceinline__ float tf32_rn(float v) {
    float r;
    asm("cvt.rna.tf32.f32 %0, %1;" : "=f"(r) : "f"(v));
    return r;
}
__device__ __forceinline__ void cp16(uint32_t s, const void* g) {
    asm volatile("cp.async.cg.shared.global [%0], [%1], 16;" :: "r"(s), "l"(g));
}
#define CP_COMMIT() asm volatile("cp.async.commit_group;" ::: "memory")
#define CP_WAIT1()  asm volatile("cp.async.wait_group 1;" ::: "memory")

// ---------------------------------------------------------------------------
// Prepass: permute W_dense [K,N] into fragment order + tf32 round.
// ---------------------------------------------------------------------------
__global__ void pack_wd_kernel(const float* __restrict__ Wd) {
    const int n = blockIdx.x * 256 + threadIdx.x;   // 4 blocks x 256
    const int k = blockIdx.y;                       // 1024
    const float v = tf32_rn(Wd[(size_t)k * N_SZ + n]);
    const int nb = n >> 4, jj = (n >> 3) & 1, g = n & 7;
    const int ks = k >> 3, kk = k & 7, t4 = kk & 3, h = kk >> 2;
    g_WdT[(size_t)nb * 16384 + ks * 128 + (g * 4 + t4) * 4 + jj * 2 + h] = v;
}

// ---------------------------------------------------------------------------
// One k-step: warp tile 32(M) x 64(N) = 2 m-tiles x 8 n-tiles.
// B fragments come from packed smem as 4x LDS.128.
// ---------------------------------------------------------------------------
__device__ __forceinline__ void compute_kstep(
    const float* __restrict__ As_, const float* __restrict__ Bs_,
    int warp_m, int warp_n, int lane, int g, int t4, int ks, float c[2][8][4]) {
    uint32_t a[2][4];
#pragma unroll
    for (int i = 0; i < 2; ++i) {
        const int r = warp_m * 32 + i * 16 + g;
        a[i][0] = __float_as_uint(As_[r * SA + ks * 8 + t4]);
        a[i][1] = __float_as_uint(As_[(r + 8) * SA + ks * 8 + t4]);
        a[i][2] = __float_as_uint(As_[r * SA + ks * 8 + t4 + 4]);
        a[i][3] = __float_as_uint(As_[(r + 8) * SA + ks * 8 + t4 + 4]);
    }
    float4 bv[4];
#pragma unroll
    for (int i = 0; i < 4; ++i)
        bv[i] = *(const float4*)(Bs_ + (warp_n * 4 + i) * 512 + ks * 128 + lane * 4);
#pragma unroll
    for (int i4 = 0; i4 < 4; ++i4) {
        const uint32_t b00 = __float_as_uint(bv[i4].x), b01 = __float_as_uint(bv[i4].y);
        const uint32_t b10 = __float_as_uint(bv[i4].z), b11 = __float_as_uint(bv[i4].w);
#pragma unroll
        for (int i = 0; i < 2; ++i) {
            asm volatile(
                "mma.sync.aligned.m16n8k8.row.col.f32.tf32.tf32.f32 "
                "{%0,%1,%2,%3}, {%4,%5,%6,%7}, {%8,%9}, {%0,%1,%2,%3};"
                : "+f"(c[i][i4 * 2][0]), "+f"(c[i][i4 * 2][1]),
                  "+f"(c[i][i4 * 2][2]), "+f"(c[i][i4 * 2][3])
                : "r"(a[i][0]), "r"(a[i][1]), "r"(a[i][2]), "r"(a[i][3]),
                  "r"(b00), "r"(b01));
            asm volatile(
                "mma.sync.aligned.m16n8k8.row.col.f32.tf32.tf32.f32 "
                "{%0,%1,%2,%3}, {%4,%5,%6,%7}, {%8,%9}, {%0,%1,%2,%3};"
                : "+f"(c[i][i4 * 2 + 1][0]), "+f"(c[i][i4 * 2 + 1][1]),
                  "+f"(c[i][i4 * 2 + 1][2]), "+f"(c[i][i4 * 2 + 1][3])
                : "r"(a[i][0]), "r"(a[i][1]), "r"(a[i][2]), "r"(a[i][3]),
                  "r"(b10), "r"(b11));
        }
    }
}

// ---------------------------------------------------------------------------
// Main GEMM kernel.  SMEM: 3 stages of [A: MT x SA | B packed: 4096 floats].
// ---------------------------------------------------------------------------
__global__ void __launch_bounds__(THREADS, 2)
enc_gemm_kernel(const int* __restrict__ x, const float* __restrict__ We,
                const float* __restrict__ be, const float* __restrict__ bd,
                float* __restrict__ out) {
    extern __shared__ float smem[];
    const uint32_t sbase = smem_u32(smem);

    const int tid = threadIdx.x;
    const int wid = tid >> 5, lane = tid & 31;
    const int g = lane >> 2, t4 = lane & 3;
    const int warp_m = wid & 3;      // 4 x 32 = 128 M
    const int warp_n = wid >> 2;     // 2 x 64 = 128 N
    const int n0 = blockIdx.x * NT;
    const int m0 = blockIdx.y * MT;

    // A-gather mapping: 2 threads per M row, 4 positions (16 floats) each.
    const int arow = tid >> 1, ahalf = tid & 1;
    const int* xptr = x + (size_t)(m0 + arow) * P_SZ + ahalf * 4;
    const float4* We4 = (const float4*)We;
    const float be0 = be[0], be1 = be[1], be2 = be[2], be3 = be[3];
    const uint32_t aDstOff = (uint32_t)arow * (SA * 4u) + (uint32_t)ahalf * 64u;

    // B-copy: 1024 x 16B per chunk / 256 threads = 4 each, fragment-packed src.
    const float* bsrc = g_WdT + (size_t)(n0 >> 4) * 16384;

    float c[2][8][4];
#pragma unroll
    for (int i = 0; i < 2; ++i)
#pragma unroll
        for (int j = 0; j < 8; ++j)
#pragma unroll
            for (int q = 0; q < 4; ++q) c[i][j][q] = 0.0f;

    auto stageA = [&](int s) -> const float* { return smem + (size_t)s * STAGE_F; };
    auto stageB = [&](int s) -> const float* { return smem + (size_t)s * STAGE_F + A_ST; };
    auto stageAaddr = [&](int s) -> uint32_t { return sbase + (uint32_t)s * (STAGE_F * 4u); };
    auto stageBaddr = [&](int s) -> uint32_t { return sbase + (uint32_t)s * (STAGE_F * 4u) + A_ST * 4u; };

    auto copyB = [&](int ch, int s) {
        const uint32_t bA = stageBaddr(s);
        const float* src = bsrc + (size_t)ch * 512;
#pragma unroll
        for (int i = 0; i < 4; ++i) {
            const int cc = tid * 4 + i;
            const int nb = cc >> 7, rem = cc & 127;
            cp16(bA + (uint32_t)nb * 2048u + (uint32_t)rem * 16u,
                 src + (size_t)nb * 16384 + rem * 4);
        }
    };
    auto stsA = [&](int s, int p, float4 e) {
        const uint32_t vx = __float_as_uint(tf32_rn(e.x + be0));
        const uint32_t vy = __float_as_uint(tf32_rn(e.y + be1));
        const uint32_t vz = __float_as_uint(tf32_rn(e.z + be2));
        const uint32_t vw = __float_as_uint(tf32_rn(e.w + be3));
        asm volatile("st.shared.v4.b32 [%0], {%1,%2,%3,%4};"
                     :: "r"(stageAaddr(s) + aDstOff + (uint32_t)p * 16u),
                        "r"(vx), "r"(vy), "r"(vz), "r"(vw) : "memory");
    };
    auto gatherA = [&](int ch, int s) {
        const int4 xi = *(const int4*)(xptr + ch * 8);
        stsA(s, 0, __ldg(We4 + xi.x));
        stsA(s, 1, __ldg(We4 + xi.y));
        stsA(s, 2, __ldg(We4 + xi.z));
        stsA(s, 3, __ldg(We4 + xi.w));
    };

    // ---- prologue ----
    gatherA(0, 0);
    copyB(0, 0); CP_COMMIT();
    copyB(1, 1); CP_COMMIT();

    // ---- mainloop ----
    for (int ch = 0; ch < NCHUNK; ++ch) {
        const int st = ch % 3;
        const bool more = (ch + 1 < NCHUNK);

        CP_WAIT1();              // B(ch) landed
        __syncthreads();         // A(ch) visible; stage (ch+2)%3 free

        if (ch + 2 < NCHUNK) copyB(ch + 2, (ch + 2) % 3);
        CP_COMMIT();

        int4 xi = {0, 0, 0, 0};
        if (more) xi = *(const int4*)(xptr + (ch + 1) * 8);

        const float* As_ = stageA(st);
        const float* Bs_ = stageB(st);

        compute_kstep(As_, Bs_, warp_m, warp_n, lane, g, t4, 0, c);
        compute_kstep(As_, Bs_, warp_m, warp_n, lane, g, t4, 1, c);

        float4 e0, e1, e2, e3;
        if (more) {
            e0 = __ldg(We4 + xi.x); e1 = __ldg(We4 + xi.y);
            e2 = __ldg(We4 + xi.z); e3 = __ldg(We4 + xi.w);
        }

        compute_kstep(As_, Bs_, warp_m, warp_n, lane, g, t4, 2, c);
        compute_kstep(As_, Bs_, warp_m, warp_n, lane, g, t4, 3, c);

        if (more) {
            const int ns = (ch + 1) % 3;
            stsA(ns, 0, e0); stsA(ns, 1, e1);
            stsA(ns, 2, e2); stsA(ns, 3, e3);
        }
    }

    // ---- epilogue: accum + b_dense -> out ----
#pragma unroll
    for (int i = 0; i < 2; ++i) {
        const size_t r0 = (size_t)(m0 + warp_m * 32 + i * 16 + g);
#pragma unroll
        for (int j = 0; j < 8; ++j) {
            const int col = n0 + warp_n * 64 + j * 8 + t4 * 2;
            const float2 bb = *(const float2*)(bd + col);
            float2 v0, v1;
            v0.x = c[i][j][0] + bb.x;  v0.y = c[i][j][1] + bb.y;
            v1.x = c[i][j][2] + bb.x;  v1.y = c[i][j][3] + bb.y;
            *(float2*)(out + r0 * N_SZ + col)       = v0;
            *(float2*)(out + (r0 + 8) * N_SZ + col) = v1;
        }
    }
}

// ---------------------------------------------------------------------------
// kernel_launch
// ---------------------------------------------------------------------------
extern "C" void kernel_launch(void* const* d_in, const int* in_sizes, int n_in,
                              void* d_out, int out_size) {
    const int*   x  = (const int*)d_in[0];
    const float* We = (const float*)d_in[1];
    const float* be = (const float*)d_in[2];
    const float* Wd = (const float*)d_in[3];
    const float* bd = (const float*)d_in[4];
    float* out = (float*)d_out;

    cudaStreamCaptureStatus cs = cudaStreamCaptureStatusNone;
    cudaError_t qerr = cudaStreamIsCapturing((cudaStream_t)0, &cs);
    const bool capturing = (qerr != cudaSuccess) || (cs != cudaStreamCaptureStatusNone);
    if (!capturing) {
        cudaFuncSetAttribute(enc_gemm_kernel,
                             cudaFuncAttributeMaxDynamicSharedMemorySize, SMEM_BYTES);
    }
    (void)cudaGetLastError();

    pack_wd_kernel<<<dim3(N_SZ / 256, K_SZ), 256>>>(Wd);
    enc_gemm_kernel<<<dim3(N_SZ / NT, B_SZ / MT), THREADS, SMEM_BYTES>>>(x, We, be, bd, out);
}